// round 7
// baseline (speedup 1.0000x reference)
#include <cuda_runtime.h>

// out[i,j,k] = C[i,j,k] * x[i,j]
// B=4096, INPUT_SIZE=512, EMBED_DIM=64 -> n = 2^27 floats, n4 = 2^25 float4
//
// v7: identical geometry to best (512 thr x 8 unroll, 64KB block tiles),
// single change: __stcs -> __stwt (write-through). Hypothesis: in-order
// write-through gives the memory controller long same-direction bursts
// instead of hash-ordered L2 evictions, cutting read/write turnaround.

#define THREADS 512
#define UNROLL  8

__global__ __launch_bounds__(THREADS)
void bcast_mul_exact(const float* __restrict__ x,
                     const float4* __restrict__ C4,
                     float4* __restrict__ out4) {
    const unsigned base = blockIdx.x * (THREADS * UNROLL) + threadIdx.x;

    float4 c[UNROLL];
    float  s[UNROLL];
#pragma unroll
    for (int j = 0; j < UNROLL; j++) {
        unsigned i = base + j * THREADS;
        c[j] = __ldcs(&C4[i]);
        s[j] = __ldg(&x[i >> 4]);          // 16 float4-groups per x scalar
    }
#pragma unroll
    for (int j = 0; j < UNROLL; j++) {
        unsigned i = base + j * THREADS;
        float4 o;
        o.x = c[j].x * s[j];
        o.y = c[j].y * s[j];
        o.z = c[j].z * s[j];
        o.w = c[j].w * s[j];
        __stwt(&out4[i], o);               // write-through, in-order stream
    }
}

__global__ void bcast_mul_generic(const float* __restrict__ x,
                                  const float4* __restrict__ C4,
                                  float4* __restrict__ out4,
                                  unsigned n4) {
    unsigned i = blockIdx.x * blockDim.x + threadIdx.x;
    if (i < n4) {
        float s = __ldg(&x[i >> 4]);
        float4 c = __ldcs(&C4[i]);
        float4 o;
        o.x = c.x * s; o.y = c.y * s; o.z = c.z * s; o.w = c.w * s;
        __stwt(&out4[i], o);
    }
}

extern "C" void kernel_launch(void* const* d_in, const int* in_sizes, int n_in,
                              void* d_out, int out_size) {
    const float* x;
    const float* C;
    if (in_sizes[0] < in_sizes[1]) {
        x = (const float*)d_in[0];
        C = (const float*)d_in[1];
    } else {
        x = (const float*)d_in[1];
        C = (const float*)d_in[0];
    }

    unsigned n4 = (unsigned)((long long)out_size >> 2);   // 33,554,432
    const unsigned per_block = THREADS * UNROLL;          // 4096

    if (n4 % per_block == 0) {
        bcast_mul_exact<<<n4 / per_block, THREADS>>>(
            x, (const float4*)C, (float4*)d_out);
    } else {
        bcast_mul_generic<<<(n4 + 255) / 256, 256>>>(
            x, (const float4*)C, (float4*)d_out, n4);
    }
}

// round 8
// speedup vs baseline: 1.0166x; 1.0166x over previous
#include <cuda_runtime.h>

// out[i,j,k] = C[i,j,k] * x[i,j]
// B=4096, INPUT_SIZE=512, EMBED_DIM=64 -> n = 2^27 floats, n4 = 2^25 float4
//
// FINAL kernel (best measured: 157.1us wall, 6.75 TB/s = 85% of HBM spec).
//  - 512 threads x 8 unroll, block-contiguous 4096-float4 (64KB r + 64KB w) tiles
//  - exact-division fast kernel, zero predication; generic fallback for safety
//  - __ldcs on C (read-once), __stcs on out (write-once evict-first; beats
//    __stwt by ~2%, tested R7), __ldg on x (L2-resident, 64x reuse)
// Search exhausted (R1-R7): MLP {1,4,8,16}, threads {256,512}, tile shapes,
// store policies all plateau at 6.67-6.78 TB/s with minimal traffic (1.032 GB).
// The binding resource is achieved HBM bandwidth on a mixed r/w stream.

#define THREADS 512
#define UNROLL  8

__global__ __launch_bounds__(THREADS)
void bcast_mul_exact(const float* __restrict__ x,
                     const float4* __restrict__ C4,
                     float4* __restrict__ out4) {
    const unsigned base = blockIdx.x * (THREADS * UNROLL) + threadIdx.x;

    float4 c[UNROLL];
    float  s[UNROLL];
#pragma unroll
    for (int j = 0; j < UNROLL; j++) {
        unsigned i = base + j * THREADS;
        c[j] = __ldcs(&C4[i]);
        s[j] = __ldg(&x[i >> 4]);          // 16 float4-groups per x scalar
    }
#pragma unroll
    for (int j = 0; j < UNROLL; j++) {
        unsigned i = base + j * THREADS;
        float4 o;
        o.x = c[j].x * s[j];
        o.y = c[j].y * s[j];
        o.z = c[j].z * s[j];
        o.w = c[j].w * s[j];
        __stcs(&out4[i], o);
    }
}

__global__ void bcast_mul_generic(const float* __restrict__ x,
                                  const float4* __restrict__ C4,
                                  float4* __restrict__ out4,
                                  unsigned n4) {
    unsigned i = blockIdx.x * blockDim.x + threadIdx.x;
    if (i < n4) {
        float s = __ldg(&x[i >> 4]);
        float4 c = __ldcs(&C4[i]);
        float4 o;
        o.x = c.x * s; o.y = c.y * s; o.z = c.z * s; o.w = c.w * s;
        __stcs(&out4[i], o);
    }
}

extern "C" void kernel_launch(void* const* d_in, const int* in_sizes, int n_in,
                              void* d_out, int out_size) {
    const float* x;
    const float* C;
    if (in_sizes[0] < in_sizes[1]) {
        x = (const float*)d_in[0];
        C = (const float*)d_in[1];
    } else {
        x = (const float*)d_in[1];
        C = (const float*)d_in[0];
    }

    unsigned n4 = (unsigned)((long long)out_size >> 2);   // 33,554,432
    const unsigned per_block = THREADS * UNROLL;          // 4096

    if (n4 % per_block == 0) {
        bcast_mul_exact<<<n4 / per_block, THREADS>>>(
            x, (const float4*)C, (float4*)d_out);
    } else {
        bcast_mul_generic<<<(n4 + 255) / 256, 256>>>(
            x, (const float4*)C, (float4*)d_out, n4);
    }
}